// round 1
// baseline (speedup 1.0000x reference)
#include <cuda_runtime.h>

// rosa_emb_layer: B=8, T=2048, V=50257, C=768
// inputs: d_in[0] = idx (B,T) int32, d_in[1] = emb (V,C) float32
// output: (B,T,C) float32
//
// L[i,j] = longest common suffix of x[..i], x[..j] (j < i). Reference argmax of
// L + j*1e-5 == integer max of (L<<11)|j (L<=2048 fits, tie-break larger j).
// Random tokens => matches are rare; brute-force equality scan from smem,
// extend backward only on hit. One warp per (b,i), fused embedding gather.

#define TT 2048
#define BB 8
#define CC 768
#define WPB 8  // warps per CTA

__global__ __launch_bounds__(256, 8)
void rosa_emb_kernel(const int* __restrict__ idx,
                     const float* __restrict__ emb,
                     float* __restrict__ out) {
    __shared__ int xs[TT];

    const int cta_per_b = TT / WPB;               // 256
    const int b      = blockIdx.x / cta_per_b;
    const int i_base = (blockIdx.x % cta_per_b) * WPB;
    const int tid  = threadIdx.x;
    const int w    = tid >> 5;
    const int lane = tid & 31;

    // Cooperatively load this batch's token row (8 KB) into shared memory.
    const int4* g  = (const int4*)(idx + (size_t)b * TT);
    int4*       s4 = (int4*)xs;
    #pragma unroll
    for (int k = tid; k < TT / 4; k += 256) s4[k] = g[k];
    __syncthreads();

    const int i  = i_base + w;
    const int xi = xs[i];

    // best = (L << 11) | j   (L in [1,2048], j in [0,2047]); 0 == no match.
    int best = 0;

    // Lanes cover j in [0, i) with int4 chunks: lane -> j0 = 4*lane + 128*k.
    for (int j0 = lane * 4; j0 < i; j0 += 128) {
        const int4 v = s4[j0 >> 2];
        const bool m0 = (v.x == xi);                    // j0 < i guaranteed
        const bool m1 = (v.y == xi) & (j0 + 1 < i);
        const bool m2 = (v.z == xi) & (j0 + 2 < i);
        const bool m3 = (v.w == xi) & (j0 + 3 < i);
        if (m0 | m1 | m2 | m3) {                        // rare (~1/12500 per elt)
            #pragma unroll
            for (int c = 0; c < 4; c++) {
                const bool m = (c == 0) ? m0 : (c == 1) ? m1 : (c == 2) ? m2 : m3;
                if (m) {
                    const int j = j0 + c;
                    int L = 1, t = 1;
                    while (t <= j && xs[i - t] == xs[j - t]) { ++L; ++t; }
                    const int packed = (L << 11) | j;
                    if (packed > best) best = packed;
                }
            }
        }
    }

    // Warp max-reduce the packed (L, j) score.
    #pragma unroll
    for (int o = 16; o; o >>= 1)
        best = max(best, __shfl_xor_sync(0xffffffffu, best, o));

    // Fused epilogue: this warp writes its own (b,i) output row of 768 floats.
    float4* orow = (float4*)(out + ((size_t)b * TT + i) * CC);
    if (best < (1 << 11)) {
        // no match -> zero row
        const float4 z = make_float4(0.f, 0.f, 0.f, 0.f);
        #pragma unroll
        for (int k = lane; k < CC / 4; k += 32) orow[k] = z;
    } else {
        const int bj   = best & 2047;
        int pidx = bj + 1; if (pidx > TT - 1) pidx = TT - 1;
        const int tok  = xs[pidx];
        const float4* erow = (const float4*)(emb + (size_t)tok * CC);
        #pragma unroll
        for (int k = lane; k < CC / 4; k += 32) orow[k] = erow[k];
    }
}

extern "C" void kernel_launch(void* const* d_in, const int* in_sizes, int n_in,
                              void* d_out, int out_size) {
    const int*   idx = (const int*)d_in[0];
    const float* emb = (const float*)d_in[1];
    float*       out = (float*)d_out;

    const int grid = BB * (TT / WPB);   // 2048 CTAs, 256 threads each
    rosa_emb_kernel<<<grid, 256>>>(idx, emb, out);
}